// round 11
// baseline (speedup 1.0000x reference)
#include <cuda_runtime.h>
#include <math.h>

// ---------------------------------------------------------------------------
// PhotonicDelayReservoirAdaptive — sparse delay-tap reservoir scan, sm_103a.
//
//   fb[b,s]  = sum_k softmax(tapw)[k] * sum_r h[b, t-d_k, r] * W_fb[k,r,s]
//   h_new    = 0.9*h + 0.1*tanh(x[b,t]*W_in[s] + fb[b,s] + bias[s])
//
// R10 (= R7/R9 design, schedule moved to gmem/L1) — NO cross-CTA sync, and
// NO large dynamic SMEM (suspected cause of the R7/R9 container failures):
//  * 64 independent CTAs, one full batch each, 256 threads (thread = column).
//  * Per-step state exchange is CTA-local: static hist[2][5*256] double
//    buffer in SMEM (10 KB); slot0 = row t-1 (written by this CTA last
//    step), slots 1-4 = rows t-{4,24,96,168} staged from registers
//    prefetched one step ahead from the CTA's own write-once gmem history
//    (plain loads; L1-resident). ONE __syncthreads per step.
//  * Schedule: 4-byte entries = f32 value (softmax tap weight folded,
//    round-to-nearest at bit 11) | 11-bit hist index (k*256+r) in the low
//    mantissa bits; perturbation <= 2^-13 rel -> output err ~1e-4 (tol 1e-3).
//    Stored round-pair interleaved in GMEM, read per step via __ldg as
//    coalesced 256B/warp LDG.64 (identical for all CTAs -> L2/L1 resident).
//  * Bank-rotation: builder counting-sorts each column's entries by
//    (r - lane) & 31 so the 32 lanes' hist-gather banks stagger per round.
//    Pads are neutral (denormal value, bank = lane).
// ---------------------------------------------------------------------------

#define T_LEN   2048
#define R_DIM   256
#define N_TAPS  5
#define CAP_R   200        // max rounds/column; nnz ~ Bin(1280,0.1): 128 + 6.7 sigma
#define NTH     256
#define NBATCH  64

#define SCHED_WORDS (8 * CAP_R * 32)            // 51200 uints = 204800 B

__device__ __align__(16) unsigned g_sched[SCHED_WORDS];
__device__ int g_R[8];

// word index for (warp w, position pos, lane l), round-pair interleaved:
// pair = pos>>1 occupies 64 consecutive words; lane l holds words
// [pair*64 + l*2 + 0, pair*64 + l*2 + 1] = rounds {2*pair, 2*pair+1}.
__device__ __forceinline__ int sched_word(int w, int pos, int l) {
    return w * (CAP_R * 32) + (pos >> 1) * 64 + l * 2 + (pos & 1);
}

// ---------------------------------------------------------------------------
// Builder: 1 CTA, 256 threads, thread = output column s (warp w = s/32,
// lane l = s%32). Counting-sort column s's nonzeros by (r - l) & 31 and
// scatter into the interleaved schedule.
// ---------------------------------------------------------------------------
__global__ void build_kernel(const float* __restrict__ W_fb,
                             const float* __restrict__ tapw) {
    __shared__ int scnt[NTH][32];   // per-thread 32-bucket counters / starts
    __shared__ int swR[8];

    const int s = threadIdx.x;
    const int w = s >> 5, l = s & 31;

    // softmax of tap weights (redundant per thread, cheap, exact)
    float tw[N_TAPS];
    {
        float m = tapw[0];
        #pragma unroll
        for (int k = 1; k < N_TAPS; k++) m = fmaxf(m, tapw[k]);
        float sum = 0.f;
        #pragma unroll
        for (int k = 0; k < N_TAPS; k++) { tw[k] = expf(tapw[k] - m); sum += tw[k]; }
        #pragma unroll
        for (int k = 0; k < N_TAPS; k++) tw[k] /= sum;
    }

    if (s < 8) swR[s] = 0;
    // pad-fill: value bits = lane (denormal ~0 after FTZ, hist bank = lane)
    for (int i = s; i < SCHED_WORDS; i += NTH) g_sched[i] = (unsigned)((i >> 1) & 31);
    #pragma unroll
    for (int b = 0; b < 32; b++) scnt[s][b] = 0;
    __syncthreads();

    // pass 1: bucket counts (coalesced: consecutive s across lanes)
    int cnt = 0;
    for (int k = 0; k < N_TAPS; k++)
        for (int r = 0; r < R_DIM; r++) {
            float v = W_fb[(k * R_DIM + r) * R_DIM + s];
            if (v != 0.f) { scnt[s][(r - l) & 31]++; cnt++; }
        }
    if (cnt > CAP_R) cnt = CAP_R;   // statistically impossible; safety clamp

    // exclusive prefix over own 32 buckets -> starts
    int acc = 0;
    #pragma unroll
    for (int b = 0; b < 32; b++) { int c = scnt[s][b]; scnt[s][b] = acc; acc += c; }
    atomicMax(&swR[w], cnt);
    __syncthreads();   // pad-fill complete, swR final

    // pass 2: scatter (value rounded to nearest at bit 11, idx in low 11 bits)
    for (int k = 0; k < N_TAPS; k++) {
        const float twk = tw[k];
        for (int r = 0; r < R_DIM; r++) {
            float v = W_fb[(k * R_DIM + r) * R_DIM + s];
            if (v != 0.f) {
                int pos = scnt[s][(r - l) & 31]++;
                if (pos < CAP_R) {
                    unsigned vb = __float_as_uint(v * twk);
                    vb = (vb + 0x400u) & ~0x7FFu;          // RTN @ bit 11
                    g_sched[sched_word(w, pos, l)] = vb | (unsigned)(k * R_DIM + r);
                }
            }
        }
    }
    if (s < 8) g_R[s] = swR[s];
}

// ---------------------------------------------------------------------------
// Main: 64 independent CTAs (one per batch), 256 threads (thread = column s).
// Static SMEM only (10 KB hist double buffer).
// ---------------------------------------------------------------------------
__global__ void __launch_bounds__(NTH, 1)
reservoir_kernel(const float* __restrict__ x,
                 const float* __restrict__ W_in,
                 const float* __restrict__ bias,
                 float* __restrict__ out) {
    __shared__ float hist[2][5 * R_DIM];   // 10240 B

    const int s = threadIdx.x;
    const int w = s >> 5, l = s & 31;
    const int b = blockIdx.x;

    for (int i = s; i < 2 * 5 * R_DIM; i += NTH) hist[0][i] = 0.f;  // both bufs

    const int R  = g_R[w];                // per-warp trip count (uniform in warp)
    const int RP = (R + 1) >> 1;          // round pairs (pads are neutral)
    const float w_in_s = W_in[s];
    const float bias_s = bias[s];
    const float* xr = x + (size_t)b * T_LEN;
    float* ob = out + (size_t)b * T_LEN * R_DIM;

    float h  = 0.f;
    float xc = __ldg(xr);                 // x[b][0]
    __syncthreads();

    // per-lane pointer to its pair stream: element p -> rounds {2p, 2p+1};
    // stride between pairs = 32 uint2 (256 B, coalesced across the warp)
    const uint2* sp2 = (const uint2*)(g_sched + w * (CAP_R * 32)) + l;

    for (int t = 0; t < T_LEN; t++) {
        const float* cur = hist[t & 1];
        float* nxt = hist[(t + 1) & 1];

        // prefetch rows for step t+1 (d>=4 taps; written >=3 steps ago by
        // THIS CTA -> plain loads, mostly L1 hits) + next x. Latency hides
        // under the gather below.
        float p0 = (t >= 3)   ? ob[(size_t)(t - 3)   * R_DIM + s] : 0.f;
        float p1 = (t >= 23)  ? ob[(size_t)(t - 23)  * R_DIM + s] : 0.f;
        float p2 = (t >= 95)  ? ob[(size_t)(t - 95)  * R_DIM + s] : 0.f;
        float p3 = (t >= 167) ? ob[(size_t)(t - 167) * R_DIM + s] : 0.f;
        float xn = (t + 1 < T_LEN) ? __ldg(xr + t + 1) : 0.f;

        // sparse gather: one coalesced LDG.64 per round pair (L1-resident
        // schedule), two hist LDS per pair, dual accumulators
        float a0 = 0.f, a1 = 0.f;
        #pragma unroll 2
        for (int p = 0; p < RP; p++) {
            const uint2 e = __ldg(&sp2[p * 32]);
            a0 = fmaf(__uint_as_float(e.x & ~0x7FFu), cur[e.x & 0x7FFu], a0);
            a1 = fmaf(__uint_as_float(e.y & ~0x7FFu), cur[e.y & 0x7FFu], a1);
        }

        // leaky tanh update + output store (coalesced 1 KB contiguous row)
        h = 0.9f * h + 0.1f * tanhf(fmaf(xc, w_in_s, a0 + a1) + bias_s);
        ob[(size_t)t * R_DIM + s] = h;

        // stage next step's hist: slot0 = row t (d=1), slots 1-4 = the
        // prefetched rows t-3, t-23, t-95, t-167 (= (t+1)-{4,24,96,168})
        nxt[s]             = h;
        nxt[1 * R_DIM + s] = p0;
        nxt[2 * R_DIM + s] = p1;
        nxt[3 * R_DIM + s] = p2;
        nxt[4 * R_DIM + s] = p3;
        xc = xn;

        __syncthreads();   // the ONLY per-step synchronization
    }
}

// ---------------------------------------------------------------------------
extern "C" void kernel_launch(void* const* d_in, const int* in_sizes, int n_in,
                              void* d_out, int out_size) {
    const float* x           = (const float*)d_in[0];  // (64, 2048, 1)
    const float* W_in        = (const float*)d_in[1];  // (256, 1)
    const float* W_fb        = (const float*)d_in[2];  // (5, 256, 256)
    const float* tap_weights = (const float*)d_in[3];  // (5,)
    const float* bias        = (const float*)d_in[4];  // (256,)
    float* out = (float*)d_out;                        // (64, 2048, 256)

    (void)in_sizes; (void)n_in; (void)out_size;

    build_kernel<<<1, NTH>>>(W_fb, tap_weights);
    reservoir_kernel<<<NBATCH, NTH>>>(x, W_in, bias, out);
}

// round 13
// speedup vs baseline: 2.7559x; 2.7559x over previous
#include <cuda_runtime.h>
#include <math.h>

// ---------------------------------------------------------------------------
// PhotonicDelayReservoirAdaptive — sparse delay-tap reservoir scan, sm_103a.
//
//   fb[b,s]  = sum_k softmax(tapw)[k] * sum_r h[b, t-d_k, r] * W_fb[k,r,s]
//   h_new    = 0.9*h + 0.1*tanh(x[b,t]*W_in[s] + fb[b,s] + bias[s])
//
// R12 — no cross-CTA sync, NO dynamic SMEM (>200KB dynamic SMEM kills the
// bench container; 3/3 correlation), L1-disciplined schedule streaming:
//  * 64 independent CTAs (1 batch each), 512 threads = 16 warps (4/SMSP).
//  * Warp wg owns 16 columns; column split across 2 sub-lanes by hist-bank
//    PARITY (sub0 even banks, sub1 odd -> the two subs can never collide),
//    each sub-list counting-sorted by rotated bank key (staggers the 16
//    lanes of a parity class across the 16 banks of that parity).
//  * Schedule in GMEM, pair-interleaved [wg][pair][lane][2]: one coalesced
//    256B LDG.64 per warp per pair, via __ldg -> L1-cached. Accessed
//    footprint ~150-185KB; history reads use __ldcg (L2-direct, no L1
//    pollution) so the schedule is the ONLY L1 resident -> steady L1 hits.
//  * Entry = f32 value (softmax tap weight folded, RTN at bit 11) | 11-bit
//    hist index (k*256+r). Measured rel_err 8e-6 with this packing (R10).
//  * Per-THREAD trip counts (pads never read; R10 read per-warp max).
//  * hist[2][5*256] static SMEM double buffer; slot0 = row t-1 written
//    locally; slots 1-4 = rows t-{4,24,96,168} register-prefetched one step
//    early from this CTA's own write-once gmem history via __ldcg.
//    ONE __syncthreads per step.
// ---------------------------------------------------------------------------

#define T_LEN     2048
#define R_DIM     256
#define N_TAPS    5
#define NTH       512
#define NWARP     16
#define NBATCH    64
#define CAP_SUB   96       // entries per sub-list: mean 64, sigma 7.6 -> +4.2s
#define CAP_PAIR  48

#define SCHED_WORDS (NWARP * CAP_PAIR * 64)   // 49152 words = 196608 B

__device__ __align__(16) unsigned g_sched[SCHED_WORDS];
__device__ int g_subR[NTH];    // entries in sub-list of (wg, lane)

// ---------------------------------------------------------------------------
// Builder: 1 CTA, 256 threads, thread = output column c (wg = c/16,
// cl = c%16). Bucket = parity(r) * 16 + rotated key (((r>>1)&15) - cl)&15;
// counting-sort and scatter into the pair-interleaved schedule.
// ---------------------------------------------------------------------------
__global__ void build_kernel(const float* __restrict__ W_fb,
                             const float* __restrict__ tapw) {
    __shared__ int scnt[R_DIM][32];   // [col][par*16 + key]

    const int c  = threadIdx.x;
    const int wg = c >> 4;
    const int cl = c & 15;

    // softmax of tap weights (exact, redundant per thread)
    float tw[N_TAPS];
    {
        float m = tapw[0];
        #pragma unroll
        for (int k = 1; k < N_TAPS; k++) m = fmaxf(m, tapw[k]);
        float sum = 0.f;
        #pragma unroll
        for (int k = 0; k < N_TAPS; k++) { tw[k] = expf(tapw[k] - m); sum += tw[k]; }
        #pragma unroll
        for (int k = 0; k < N_TAPS; k++) tw[k] /= sum;
    }

    // pad-fill: value bits zero above bit 11 (denormal ~0), idx = word lane
    // -> a pad read contributes ~1e-45 * h and hits bank == its lane.
    for (int i = c; i < SCHED_WORDS; i += R_DIM)
        g_sched[i] = (unsigned)((i >> 1) & 31);
    #pragma unroll
    for (int bkt = 0; bkt < 32; bkt++) scnt[c][bkt] = 0;
    __syncthreads();

    // pass 1: bucket counts (coalesced over c across lanes)
    for (int k = 0; k < N_TAPS; k++)
        for (int r = 0; r < R_DIM; r++) {
            float v = W_fb[(k * R_DIM + r) * R_DIM + c];
            if (v != 0.f) {
                int par = r & 1;
                int key = (((r >> 1) & 15) - cl) & 15;
                scnt[c][par * 16 + key]++;
            }
        }

    // exclusive prefix within each parity partition; record sub counts
    #pragma unroll
    for (int par = 0; par < 2; par++) {
        int acc = 0;
        #pragma unroll
        for (int bkt = 0; bkt < 16; bkt++) {
            int v = scnt[c][par * 16 + bkt];
            scnt[c][par * 16 + bkt] = acc;
            acc += v;
        }
        g_subR[wg * 32 + 2 * cl + par] = (acc < CAP_SUB) ? acc : CAP_SUB;
    }

    // pass 2: scatter sorted entries (value RTN @ bit 11 | 11-bit index)
    for (int k = 0; k < N_TAPS; k++) {
        const float twk = tw[k];
        for (int r = 0; r < R_DIM; r++) {
            float v = W_fb[(k * R_DIM + r) * R_DIM + c];
            if (v != 0.f) {
                int par = r & 1;
                int key = (((r >> 1) & 15) - cl) & 15;
                int j = scnt[c][par * 16 + key]++;
                if (j < CAP_SUB) {
                    unsigned vb = __float_as_uint(v * twk);
                    vb = (vb + 0x400u) & ~0x7FFu;
                    const int lane = 2 * cl + par;
                    g_sched[wg * (CAP_PAIR * 64) + (j >> 1) * 64
                            + lane * 2 + (j & 1)]
                        = vb | (unsigned)(k * R_DIM + r);
                }
            }
        }
    }
}

// ---------------------------------------------------------------------------
// Main: 64 independent CTAs (one batch each), 512 threads, static SMEM only.
// ---------------------------------------------------------------------------
__global__ void __launch_bounds__(NTH, 1)
reservoir_kernel(const float* __restrict__ x,
                 const float* __restrict__ W_in,
                 const float* __restrict__ bias,
                 float* __restrict__ out) {
    __shared__ float hist[2][5 * R_DIM];   // 10240 B static

    const int tid  = threadIdx.x;
    const int wg   = tid >> 5;
    const int lane = tid & 31;
    const int c    = wg * 16 + (lane >> 1);   // owned column
    const int b    = blockIdx.x;

    for (int i = tid; i < 2 * 5 * R_DIM; i += NTH) hist[0][i] = 0.f;

    const int myR  = g_subR[tid];
    const int myRP = (myR + 1) >> 1;          // pairs (odd: last reads 1 pad)
    const float w_in_c = W_in[c];
    const float bias_c = bias[c];
    const float* xr = x + (size_t)b * T_LEN;
    float* ob = out + (size_t)b * T_LEN * R_DIM;

    // prefetch staging roles: threads 0-255 stage slots 1,2; 256-511 slots 3,4
    const int q    = tid >> 8;
    const int col2 = tid & 255;

    float h  = 0.f;
    float xc = __ldg(xr);
    __syncthreads();

    // my pair stream: pair p at words [p*64 + lane*2, +1] (warp: 256B coalesced)
    const uint2* sp2 = (const uint2*)(g_sched + wg * (CAP_PAIR * 64)) + lane;

    for (int t = 0; t < T_LEN; t++) {
        const float* cur = hist[t & 1];
        float*       nxt = hist[(t + 1) & 1];

        // prefetch rows for step t+1 from this CTA's own write-once history
        // (__ldcg: L2-direct, keeps L1 free for the schedule) + next x
        float p0, p1;
        if (q == 0) {
            p0 = (t >= 3)  ? __ldcg(ob + (size_t)(t - 3)  * R_DIM + col2) : 0.f;
            p1 = (t >= 23) ? __ldcg(ob + (size_t)(t - 23) * R_DIM + col2) : 0.f;
        } else {
            p0 = (t >= 95)  ? __ldcg(ob + (size_t)(t - 95)  * R_DIM + col2) : 0.f;
            p1 = (t >= 167) ? __ldcg(ob + (size_t)(t - 167) * R_DIM + col2) : 0.f;
        }
        const float xn = (t + 1 < T_LEN) ? __ldg(xr + t + 1) : 0.f;

        // sparse gather: coalesced L1-resident LDG.64 + parity-sorted LDS
        float a0 = 0.f, a1 = 0.f;
        #pragma unroll 4
        for (int p = 0; p < myRP; p++) {
            const uint2 e = __ldg(&sp2[p * 32]);
            a0 = fmaf(__uint_as_float(e.x & ~0x7FFu), cur[e.x & 0x7FFu], a0);
            a1 = fmaf(__uint_as_float(e.y & ~0x7FFu), cur[e.y & 0x7FFu], a1);
        }
        float acc = a0 + a1;
        acc += __shfl_xor_sync(0xffffffffu, acc, 1);   // combine sub-lanes

        // both sub-lanes compute h (same inputs); sub0 stores
        h = 0.9f * h + 0.1f * tanhf(fmaf(xc, w_in_c, acc) + bias_c);
        if ((lane & 1) == 0) {
            ob[(size_t)t * R_DIM + c] = h;
            nxt[c] = h;                                 // slot0 = row t (d=1)
        }

        // stage slots 1-4: rows (t+1)-{4,24,96,168} = t-3, t-23, t-95, t-167
        if (q == 0) {
            nxt[1 * R_DIM + col2] = p0;
            nxt[2 * R_DIM + col2] = p1;
        } else {
            nxt[3 * R_DIM + col2] = p0;
            nxt[4 * R_DIM + col2] = p1;
        }
        xc = xn;

        __syncthreads();   // the ONLY per-step synchronization
    }
}

// ---------------------------------------------------------------------------
extern "C" void kernel_launch(void* const* d_in, const int* in_sizes, int n_in,
                              void* d_out, int out_size) {
    const float* x           = (const float*)d_in[0];  // (64, 2048, 1)
    const float* W_in        = (const float*)d_in[1];  // (256, 1)
    const float* W_fb        = (const float*)d_in[2];  // (5, 256, 256)
    const float* tap_weights = (const float*)d_in[3];  // (5,)
    const float* bias        = (const float*)d_in[4];  // (256,)
    float* out = (float*)d_out;                        // (64, 2048, 256)

    (void)in_sizes; (void)n_in; (void)out_size;

    build_kernel<<<1, R_DIM>>>(W_fb, tap_weights);
    reservoir_kernel<<<NBATCH, NTH>>>(x, W_in, bias, out);
}